// round 14
// baseline (speedup 1.0000x reference)
#include <cuda_runtime.h>
#include <math.h>

#define EMAX 200000
#define NMAX 12500
#define TE 64
#define NT 256

__device__ float g_lat[(size_t)128 * EMAX];
__device__ float g_w64[(size_t)64 * EMAX];
__device__ float g_fn [(size_t)128 * EMAX];
__device__ float g_env0[(size_t)NMAX * 128];
__device__ float g_env1[(size_t)NMAX * 128];

__device__ __forceinline__ float silu_f(float v) { return v / (1.0f + __expf(-v)); }

// Tile GEMM v3: warp covers 32 edges x (KOUT/4) cols -> per-warp smem traffic
// hits the crossbar floor (a: 128B contiguous; b: contiguous slab, both
// conflict-free). Thread: 4 edges x CPT cols, packed f32x2 accumulators.
template <int KIN, int KOUT, bool SILU, class Epi>
__device__ __forceinline__ void gemm_tile(const float* __restrict__ Xs,
                                          const float* __restrict__ Wg,
                                          float* __restrict__ Wbuf,
                                          float scale, int tid, Epi epi)
{
    constexpr int CPT = KOUT / 16;   // 8, 4 or 2 cols per thread
    constexpr int NPR = CPT / 2;     // col-pairs per thread
    unsigned long long acc[4][NPR];
#pragma unroll
    for (int i = 0; i < 4; i++)
#pragma unroll
        for (int j = 0; j < NPR; j++) acc[i][j] = 0ull;

    const int lane = tid & 31, wid = tid >> 5;
    const int e_base = (wid & 1) * 32 + (lane & 7) * 4;            // 32-edge half
    const int c_base = (wid >> 1) * (KOUT / 4) + (lane >> 3) * CPT; // 32-col quarter

    for (int kc = 0; kc < KIN; kc += 64) {
        __syncthreads();
        const int rows = (KIN - kc) < 64 ? (KIN - kc) : 64;
        {
            const float4* src = (const float4*)(Wg + (size_t)kc * KOUT);
            float4* dst = (float4*)Wbuf;
            for (int i = tid; i < rows * KOUT / 4; i += NT) dst[i] = src[i];
        }
        __syncthreads();
#pragma unroll 8
        for (int kk = 0; kk < rows; kk++) {
            float4 av = *(const float4*)(Xs + (kc + kk) * TE + e_base);
            unsigned long long a0, a1, a2, a3;
            asm("mov.b64 %0,{%1,%1};" : "=l"(a0) : "f"(av.x));
            asm("mov.b64 %0,{%1,%1};" : "=l"(a1) : "f"(av.y));
            asm("mov.b64 %0,{%1,%1};" : "=l"(a2) : "f"(av.z));
            asm("mov.b64 %0,{%1,%1};" : "=l"(a3) : "f"(av.w));
            const float* wrow = Wbuf + kk * KOUT + c_base;
            unsigned long long b[NPR];
            if (NPR == 1) {
                b[0] = *(const unsigned long long*)wrow;
            } else if (NPR == 2) {
                ulonglong2 bv = *(const ulonglong2*)wrow;
                b[0] = bv.x; b[1] = bv.y;
            } else {
                ulonglong2 bv0 = *(const ulonglong2*)wrow;
                ulonglong2 bv1 = *(const ulonglong2*)(wrow + 4);
                b[0] = bv0.x; b[1] = bv0.y; b[2] = bv1.x; b[3] = bv1.y;
            }
#pragma unroll
            for (int j = 0; j < NPR; j++) {
                asm("fma.rn.f32x2 %0,%1,%2,%0;" : "+l"(acc[0][j]) : "l"(a0), "l"(b[j]));
                asm("fma.rn.f32x2 %0,%1,%2,%0;" : "+l"(acc[1][j]) : "l"(a1), "l"(b[j]));
                asm("fma.rn.f32x2 %0,%1,%2,%0;" : "+l"(acc[2][j]) : "l"(a2), "l"(b[j]));
                asm("fma.rn.f32x2 %0,%1,%2,%0;" : "+l"(acc[3][j]) : "l"(a3), "l"(b[j]));
            }
        }
    }
#pragma unroll
    for (int j = 0; j < NPR; j++) {
        int col = c_base + 2 * j;
#pragma unroll
        for (int i = 0; i < 4; i++) {
            float lo, hi;
            asm("mov.b64 {%0,%1},%2;" : "=f"(lo), "=f"(hi) : "l"(acc[i][j]));
            lo *= scale; hi *= scale;
            if (SILU) { lo = silu_f(lo); hi = silu_f(hi); }
            epi(col, e_base + i, lo);
            epi(col + 1, e_base + i, hi);
        }
    }
    __syncthreads();
}

// ============ Kernel A: lat = mlp2(inv); w = lat@Wenv0; scatter env0 ============
// smem 101.6KB (WT aliases dead XS+H) -> 2 CTAs/SM.
__global__ void __launch_bounds__(NT, 2)
kA(const int* __restrict__ eidx, const float* __restrict__ attr,
   const float* __restrict__ inv, const float* __restrict__ W2b0,
   const float* __restrict__ W2b1, const float* __restrict__ Wenv0, int E)
{
    extern __shared__ float sm[];
    float* WBUF = sm;                 // 8192
    float* XS   = sm + 8192;          // 512
    float* H    = sm + 8704;          // 8192
    float* LAT  = sm + 16896;         // 8192
    float* ATTR = sm + 25088;         // 256
    int*   CENT = (int*)(sm + 25344); // 64
    float* WT   = sm + 8192;          // 8320 alias over XS+H (dead by gemm3)
    const int tid = threadIdx.x, e0 = blockIdx.x * TE;

    for (int i = tid; i < TE; i += NT) { int ge = e0 + i; CENT[i] = (ge < E) ? eidx[ge] : 0; }
    for (int i = tid; i < 4 * TE; i += NT) {
        int e = i >> 2, c = i & 3, ge = e0 + e;
        ATTR[c * TE + e] = (ge < E) ? attr[(size_t)ge * 4 + c] : 0.0f;
    }
    for (int i = tid; i < 8 * TE; i += NT) {
        int e = i >> 3, c = i & 7, ge = e0 + e;
        XS[c * TE + e] = (ge < E) ? inv[(size_t)ge * 8 + c] : 0.0f;
    }

    gemm_tile<8, 128, true >(XS, W2b0, WBUF, 0.35355339059327373f, tid,
        [&](int col, int e, float v) { H[col * TE + e] = v; });
    gemm_tile<128, 128, false>(H, W2b1, WBUF, 0.08838834764831845f, tid,
        [&](int col, int e, float v) { LAT[col * TE + e] = v; });

    for (int i = tid; i < 128 * TE; i += NT) {
        int e = i & 63, c = i >> 6, ge = e0 + e;
        if (ge < E) g_lat[(size_t)c * E + ge] = LAT[c * TE + e];
    }

    gemm_tile<128, 128, false>(LAT, Wenv0, WBUF, 0.08838834764831845f, tid,
        [&](int col, int e, float v) { WT[col * 65 + e] = v; });

    for (int i = tid; i < 64 * TE; i += NT) {
        int e = i & 63, c = i >> 6, ge = e0 + e;
        if (ge < E) g_w64[(size_t)c * E + ge] = WT[c * 65 + e];
    }
    for (int i = tid; i < 128 * TE; i += NT) {
        int comp = i & 127, e = i >> 7, ge = e0 + e;
        if (ge >= E) continue;
        int m = comp >> 2, cc = comp & 3;
        int row = 64 + 2 * m + (cc ? 1 : 0);
        atomicAdd(&g_env0[(size_t)CENT[e] * 128 + comp], WT[row * 65 + e] * ATTR[cc * TE + e]);
    }
}

// ============ Kernel C: tensor products, Ws0/Wv0, lat update, scatter env1 ============
__global__ void __launch_bounds__(NT, 1)
kC(const int* __restrict__ eidx, const float* __restrict__ attr,
   const float* __restrict__ Ws0, const float* __restrict__ Wv0,
   const float* __restrict__ Wlat10, const float* __restrict__ Wlat11,
   const float* __restrict__ Wenv1, int E)
{
    extern __shared__ float sm[];
    float* WBUF  = sm;                 // 8192
    float* LATSC = sm + 8192;          // 12288
    float* ENVH  = sm + 20480;         // 8320 (env0 s65 -> H s64 -> w1 s65)
    float* W64S  = sm + 28800;         // 4160 (stride 65)
    float* SIN   = sm + 32960;         // 4096
    float* VIN   = sm + 37056;         // 12288 (v_in -> new_lat)
    float* ATTR  = sm + 49344;         // 256
    int*   CENT  = (int*)(sm + 49600); // 64
    const int tid = threadIdx.x, e0 = blockIdx.x * TE;

    for (int i = tid; i < TE; i += NT) { int ge = e0 + i; CENT[i] = (ge < E) ? eidx[ge] : 0; }
    for (int i = tid; i < 4 * TE; i += NT) {
        int e = i >> 2, c = i & 3, ge = e0 + e;
        ATTR[c * TE + e] = (ge < E) ? attr[(size_t)ge * 4 + c] : 0.0f;
    }
    for (int i = tid; i < 128 * TE; i += NT) {
        int e = i & 63, c = i >> 6, ge = e0 + e;
        LATSC[c * TE + e] = (ge < E) ? g_lat[(size_t)c * E + ge] : 0.0f;
    }
    for (int i = tid; i < 64 * TE; i += NT) {
        int e = i & 63, c = i >> 6, ge = e0 + e;
        W64S[c * 65 + e] = (ge < E) ? g_w64[(size_t)c * E + ge] : 0.0f;
    }
    __syncthreads();
    for (int i = tid; i < 128 * TE; i += NT) {
        int c = i & 127, e = i >> 7;
        ENVH[c * 65 + e] = g_env0[(size_t)CENT[e] * 128 + c] * 0.25f;
    }
    __syncthreads();

    const float is3 = 0.5773502691896258f;
    for (int i = tid; i < 32 * TE; i += NT) {
        int m = i >> 6, e = i & 63;
        float a0 = ATTR[e], a1 = ATTR[TE + e], a2 = ATTR[2 * TE + e], a3 = ATTR[3 * TE + e];
        float wA = W64S[(2 * m) * 65 + e], wB = W64S[(2 * m + 1) * 65 + e];
        float x0 = wA * a0, x1 = wB * a1, x2 = wB * a2, x3 = wB * a3;
        float y0 = ENVH[(4 * m) * 65 + e],     y1 = ENVH[(4 * m + 1) * 65 + e];
        float y2 = ENVH[(4 * m + 2) * 65 + e], y3 = ENVH[(4 * m + 3) * 65 + e];
        float ss = x0 * y0;
        float vv = (x1 * y1 + x2 * y2 + x3 * y3) * is3;
        LATSC[(128 + 2 * m) * TE + e]     = ss;
        LATSC[(128 + 2 * m + 1) * TE + e] = vv;
        SIN[m * TE + e]        = ss;
        SIN[(32 + m) * TE + e] = vv;
        VIN[(0 * 64 + m) * TE + e]      = x0 * y1 * is3;
        VIN[(1 * 64 + m) * TE + e]      = x0 * y2 * is3;
        VIN[(2 * 64 + m) * TE + e]      = x0 * y3 * is3;
        VIN[(0 * 64 + 32 + m) * TE + e] = x1 * y0 * is3;
        VIN[(1 * 64 + 32 + m) * TE + e] = x2 * y0 * is3;
        VIN[(2 * 64 + 32 + m) * TE + e] = x3 * y0 * is3;
    }

    gemm_tile<64, 32, false>(SIN, Ws0, WBUF, 0.125f, tid,
        [&](int col, int e, float v) { int ge = e0 + e; if (ge < E) g_fn[(size_t)(col * 4) * E + ge] = v; });
    gemm_tile<64, 32, false>(VIN, Wv0, WBUF, 0.125f, tid,
        [&](int col, int e, float v) { int ge = e0 + e; if (ge < E) g_fn[(size_t)(col * 4 + 1) * E + ge] = v; });
    gemm_tile<64, 32, false>(VIN + 64 * TE, Wv0, WBUF, 0.125f, tid,
        [&](int col, int e, float v) { int ge = e0 + e; if (ge < E) g_fn[(size_t)(col * 4 + 2) * E + ge] = v; });
    gemm_tile<64, 32, false>(VIN + 128 * TE, Wv0, WBUF, 0.125f, tid,
        [&](int col, int e, float v) { int ge = e0 + e; if (ge < E) g_fn[(size_t)(col * 4 + 3) * E + ge] = v; });

    gemm_tile<192, 128, true >(LATSC, Wlat10, WBUF, 0.07216878364870323f, tid,
        [&](int col, int e, float v) { ENVH[col * TE + e] = v; });
    gemm_tile<128, 128, false>(ENVH, Wlat11, WBUF, 0.08838834764831845f, tid,
        [&](int col, int e, float v) { VIN[col * TE + e] = v; });

    const float c0 = 0.7071067811865476f;
    for (int i = tid; i < 128 * TE; i += NT) {
        int e = i & 63, c = i >> 6, ge = e0 + e;
        float v = c0 * (LATSC[i] + VIN[i]);
        LATSC[i] = v;
        if (ge < E) g_lat[(size_t)c * E + ge] = v;
    }

    gemm_tile<128, 64, false>(LATSC, Wenv1, WBUF, 0.08838834764831845f, tid,
        [&](int col, int e, float v) { ENVH[col * 65 + e] = v; });

    for (int i = tid; i < 128 * TE; i += NT) {
        int comp = i & 127, e = i >> 7, ge = e0 + e;
        if (ge >= E) continue;
        int m = comp >> 2, cc = comp & 3;
        int row = 2 * m + (cc ? 1 : 0);
        atomicAdd(&g_env1[(size_t)CENT[e] * 128 + comp], ENVH[row * 65 + e] * ATTR[cc * TE + e]);
    }
}

// ============ Kernel D: gather env1, final MLP, output ============
__global__ void __launch_bounds__(NT, 1)
kD(const int* __restrict__ eidx, const float* __restrict__ Wfin0,
   const float* __restrict__ Wfin1, float* __restrict__ out, int E)
{
    extern __shared__ float sm[];
    float* WBUF  = sm;                 // 8320 (weights / transpose s129)
    float* LATSC = sm + 8320;          // 12288
    float* FN    = sm + 20608;         // 8192
    float* ENVH  = sm + 28800;         // 8320
    int*   CENT  = (int*)(sm + 37120); // 64
    const int tid = threadIdx.x, e0 = blockIdx.x * TE;

    for (int i = tid; i < TE; i += NT) { int ge = e0 + i; CENT[i] = (ge < E) ? eidx[ge] : 0; }
    for (int i = tid; i < 128 * TE; i += NT) {
        int e = i & 63, c = i >> 6, ge = e0 + e;
        LATSC[c * TE + e] = (ge < E) ? g_lat[(size_t)c * E + ge] : 0.0f;
        FN[c * TE + e]    = (ge < E) ? g_fn[(size_t)c * E + ge] : 0.0f;
    }
    __syncthreads();
    for (int i = tid; i < 128 * TE; i += NT) {
        int c = i & 127, e = i >> 7;
        ENVH[c * 65 + e] = g_env1[(size_t)CENT[e] * 128 + c] * 0.25f;
    }
    __syncthreads();

    const float is3 = 0.5773502691896258f;
    for (int i = tid; i < 32 * TE; i += NT) {
        int m = i >> 6, e = i & 63;
        float f0 = FN[(4 * m) * TE + e],     f1 = FN[(4 * m + 1) * TE + e];
        float f2 = FN[(4 * m + 2) * TE + e], f3 = FN[(4 * m + 3) * TE + e];
        float y0 = ENVH[(4 * m) * 65 + e],     y1 = ENVH[(4 * m + 1) * 65 + e];
        float y2 = ENVH[(4 * m + 2) * 65 + e], y3 = ENVH[(4 * m + 3) * 65 + e];
        LATSC[(128 + 2 * m) * TE + e]     = f0 * y0;
        LATSC[(128 + 2 * m + 1) * TE + e] = (f1 * y1 + f2 * y2 + f3 * y3) * is3;
    }

    gemm_tile<192, 128, true >(LATSC, Wfin0, WBUF, 0.07216878364870323f, tid,
        [&](int col, int e, float v) { ENVH[col * TE + e] = v; });
    gemm_tile<128, 128, false>(ENVH, Wfin1, WBUF, 0.08838834764831845f, tid,
        [&](int col, int e, float v) { FN[col * TE + e] = v; });

    const float ca = 0.816496580927726f, cb = 0.5773502691896258f;
    for (int i = tid; i < 128 * TE; i += NT) {
        int e = i & 63, c = i >> 6;
        WBUF[e * 129 + c] = ca * LATSC[c * TE + e] + cb * FN[c * TE + e];
    }
    __syncthreads();
    for (int i = tid; i < 128 * TE; i += NT) {
        int c = i & 127, e = i >> 7, ge = e0 + e;
        if (ge < E) out[(size_t)ge * 128 + c] = WBUF[e * 129 + c];
    }
}

extern "C" void kernel_launch(void* const* d_in, const int* in_sizes, int n_in,
                              void* d_out, int out_size)
{
    const int*   eidx   = (const int*)d_in[0];
    const float* attr   = (const float*)d_in[1];
    const float* inv    = (const float*)d_in[2];
    const float* W2b0   = (const float*)d_in[3];
    const float* W2b1   = (const float*)d_in[4];
    const float* Wenv0  = (const float*)d_in[5];
    const float* Wlat10 = (const float*)d_in[6];
    const float* Wlat11 = (const float*)d_in[7];
    const float* Wenv1  = (const float*)d_in[8];
    const float* Ws0    = (const float*)d_in[9];
    const float* Wv0    = (const float*)d_in[10];
    const float* Wfin0  = (const float*)d_in[11];
    const float* Wfin1  = (const float*)d_in[12];

    int E = in_sizes[1] / 4;
    if (E > EMAX) E = EMAX;

    const int smemA = 25408 * (int)sizeof(float);  // 101632 -> 2 CTAs/SM
    const int smemC = 49664 * (int)sizeof(float);
    const int smemD = 37184 * (int)sizeof(float);
    static int attr_done = 0;
    if (!attr_done) {
        cudaFuncSetAttribute(kA, cudaFuncAttributeMaxDynamicSharedMemorySize, smemA);
        cudaFuncSetAttribute(kC, cudaFuncAttributeMaxDynamicSharedMemorySize, smemC);
        cudaFuncSetAttribute(kD, cudaFuncAttributeMaxDynamicSharedMemorySize, smemD);
        attr_done = 1;
    }

    void *p0, *p1;
    cudaGetSymbolAddress(&p0, g_env0);
    cudaGetSymbolAddress(&p1, g_env1);
    cudaMemsetAsync(p0, 0, (size_t)NMAX * 128 * sizeof(float), 0);
    cudaMemsetAsync(p1, 0, (size_t)NMAX * 128 * sizeof(float), 0);

    int nb = (E + TE - 1) / TE;
    kA<<<nb, NT, smemA>>>(eidx, attr, inv, W2b0, W2b1, Wenv0, E);
    kC<<<nb, NT, smemC>>>(eidx, attr, Ws0, Wv0, Wlat10, Wlat11, Wenv1, E);
    kD<<<nb, NT, smemD>>>(eidx, Wfin0, Wfin1, (float*)d_out, E);
}

// round 15
// speedup vs baseline: 1.0094x; 1.0094x over previous
#include <cuda_runtime.h>
#include <math.h>

#define EMAX 200000
#define NMAX 12500
#define TE 64
#define NT 256

__device__ float g_lat[(size_t)128 * EMAX];
__device__ float g_w64[(size_t)64 * EMAX];
__device__ float g_fn [(size_t)128 * EMAX];
__device__ float g_env0[(size_t)NMAX * 128];
__device__ float g_env1[(size_t)NMAX * 128];

__device__ __forceinline__ float silu_f(float v) { return v / (1.0f + __expf(-v)); }

// Tile GEMM v3: warp covers 32 edges x (KOUT/4) cols -> per-warp smem traffic
// hits the crossbar floor (a: 128B contiguous; b: contiguous slab, both
// conflict-free). Thread: 4 edges x CPT cols, packed f32x2 accumulators.
template <int KIN, int KOUT, bool SILU, class Epi>
__device__ __forceinline__ void gemm_tile(const float* __restrict__ Xs,
                                          const float* __restrict__ Wg,
                                          float* __restrict__ Wbuf,
                                          float scale, int tid, Epi epi)
{
    constexpr int CPT = KOUT / 16;   // 8, 4 or 2 cols per thread
    constexpr int NPR = CPT / 2;     // col-pairs per thread
    unsigned long long acc[4][NPR];
#pragma unroll
    for (int i = 0; i < 4; i++)
#pragma unroll
        for (int j = 0; j < NPR; j++) acc[i][j] = 0ull;

    const int lane = tid & 31, wid = tid >> 5;
    const int e_base = (wid & 1) * 32 + (lane & 7) * 4;            // 32-edge half
    const int c_base = (wid >> 1) * (KOUT / 4) + (lane >> 3) * CPT; // 32-col quarter

    for (int kc = 0; kc < KIN; kc += 64) {
        __syncthreads();
        const int rows = (KIN - kc) < 64 ? (KIN - kc) : 64;
        {
            const float4* src = (const float4*)(Wg + (size_t)kc * KOUT);
            float4* dst = (float4*)Wbuf;
            for (int i = tid; i < rows * KOUT / 4; i += NT) dst[i] = src[i];
        }
        __syncthreads();
#pragma unroll 8
        for (int kk = 0; kk < rows; kk++) {
            float4 av = *(const float4*)(Xs + (kc + kk) * TE + e_base);
            unsigned long long a0, a1, a2, a3;
            asm("mov.b64 %0,{%1,%1};" : "=l"(a0) : "f"(av.x));
            asm("mov.b64 %0,{%1,%1};" : "=l"(a1) : "f"(av.y));
            asm("mov.b64 %0,{%1,%1};" : "=l"(a2) : "f"(av.z));
            asm("mov.b64 %0,{%1,%1};" : "=l"(a3) : "f"(av.w));
            const float* wrow = Wbuf + kk * KOUT + c_base;
            unsigned long long b[NPR];
            if (NPR == 1) {
                b[0] = *(const unsigned long long*)wrow;
            } else if (NPR == 2) {
                ulonglong2 bv = *(const ulonglong2*)wrow;
                b[0] = bv.x; b[1] = bv.y;
            } else {
                ulonglong2 bv0 = *(const ulonglong2*)wrow;
                ulonglong2 bv1 = *(const ulonglong2*)(wrow + 4);
                b[0] = bv0.x; b[1] = bv0.y; b[2] = bv1.x; b[3] = bv1.y;
            }
#pragma unroll
            for (int j = 0; j < NPR; j++) {
                asm("fma.rn.f32x2 %0,%1,%2,%0;" : "+l"(acc[0][j]) : "l"(a0), "l"(b[j]));
                asm("fma.rn.f32x2 %0,%1,%2,%0;" : "+l"(acc[1][j]) : "l"(a1), "l"(b[j]));
                asm("fma.rn.f32x2 %0,%1,%2,%0;" : "+l"(acc[2][j]) : "l"(a2), "l"(b[j]));
                asm("fma.rn.f32x2 %0,%1,%2,%0;" : "+l"(acc[3][j]) : "l"(a3), "l"(b[j]));
            }
        }
    }
#pragma unroll
    for (int j = 0; j < NPR; j++) {
        int col = c_base + 2 * j;
#pragma unroll
        for (int i = 0; i < 4; i++) {
            float lo, hi;
            asm("mov.b64 {%0,%1},%2;" : "=f"(lo), "=f"(hi) : "l"(acc[i][j]));
            lo *= scale; hi *= scale;
            if (SILU) { lo = silu_f(lo); hi = silu_f(hi); }
            epi(col, e_base + i, lo);
            epi(col + 1, e_base + i, hi);
        }
    }
    __syncthreads();
}

// ============ Kernel A: lat = mlp2(inv); w = lat@Wenv0; scatter env0 ============
// smem 101.6KB (WT aliases dead XS+H) -> 2 CTAs/SM.
__global__ void __launch_bounds__(NT, 2)
kA(const int* __restrict__ eidx, const float* __restrict__ attr,
   const float* __restrict__ inv, const float* __restrict__ W2b0,
   const float* __restrict__ W2b1, const float* __restrict__ Wenv0, int E)
{
    extern __shared__ float sm[];
    float* WBUF = sm;                 // 8192
    float* XS   = sm + 8192;          // 512
    float* H    = sm + 8704;          // 8192
    float* LAT  = sm + 16896;         // 8192
    float* ATTR = sm + 25088;         // 256
    int*   CENT = (int*)(sm + 25344); // 64
    float* WT   = sm + 8192;          // 8320 alias over XS+H (dead by gemm3)
    const int tid = threadIdx.x, e0 = blockIdx.x * TE;

    for (int i = tid; i < TE; i += NT) { int ge = e0 + i; CENT[i] = (ge < E) ? eidx[ge] : 0; }
    for (int i = tid; i < 4 * TE; i += NT) {
        int e = i >> 2, c = i & 3, ge = e0 + e;
        ATTR[c * TE + e] = (ge < E) ? attr[(size_t)ge * 4 + c] : 0.0f;
    }
    for (int i = tid; i < 8 * TE; i += NT) {
        int e = i >> 3, c = i & 7, ge = e0 + e;
        XS[c * TE + e] = (ge < E) ? inv[(size_t)ge * 8 + c] : 0.0f;
    }

    gemm_tile<8, 128, true >(XS, W2b0, WBUF, 0.35355339059327373f, tid,
        [&](int col, int e, float v) { H[col * TE + e] = v; });
    gemm_tile<128, 128, false>(H, W2b1, WBUF, 0.08838834764831845f, tid,
        [&](int col, int e, float v) { LAT[col * TE + e] = v; });

    for (int i = tid; i < 128 * TE; i += NT) {
        int e = i & 63, c = i >> 6, ge = e0 + e;
        if (ge < E) g_lat[(size_t)c * E + ge] = LAT[c * TE + e];
    }

    gemm_tile<128, 128, false>(LAT, Wenv0, WBUF, 0.08838834764831845f, tid,
        [&](int col, int e, float v) { WT[col * 65 + e] = v; });

    for (int i = tid; i < 64 * TE; i += NT) {
        int e = i & 63, c = i >> 6, ge = e0 + e;
        if (ge < E) g_w64[(size_t)c * E + ge] = WT[c * 65 + e];
    }
    for (int i = tid; i < 128 * TE; i += NT) {
        int comp = i & 127, e = i >> 7, ge = e0 + e;
        if (ge >= E) continue;
        int m = comp >> 2, cc = comp & 3;
        int row = 64 + 2 * m + (cc ? 1 : 0);
        atomicAdd(&g_env0[(size_t)CENT[e] * 128 + comp], WT[row * 65 + e] * ATTR[cc * TE + e]);
    }
}

// ============ Kernel C: tensor products, Ws0/Wv0, lat update, scatter env1 ============
__global__ void __launch_bounds__(NT, 1)
kC(const int* __restrict__ eidx, const float* __restrict__ attr,
   const float* __restrict__ Ws0, const float* __restrict__ Wv0,
   const float* __restrict__ Wlat10, const float* __restrict__ Wlat11,
   const float* __restrict__ Wenv1, int E)
{
    extern __shared__ float sm[];
    float* WBUF  = sm;                 // 8192
    float* LATSC = sm + 8192;          // 12288
    float* ENVH  = sm + 20480;         // 8320 (env0 s65 -> H s64 -> w1 s65)
    float* W64S  = sm + 28800;         // 4160 (stride 65)
    float* SIN   = sm + 32960;         // 4096
    float* VIN   = sm + 37056;         // 12288 (v_in -> new_lat)
    float* ATTR  = sm + 49344;         // 256
    int*   CENT  = (int*)(sm + 49600); // 64
    const int tid = threadIdx.x, e0 = blockIdx.x * TE;

    for (int i = tid; i < TE; i += NT) { int ge = e0 + i; CENT[i] = (ge < E) ? eidx[ge] : 0; }
    for (int i = tid; i < 4 * TE; i += NT) {
        int e = i >> 2, c = i & 3, ge = e0 + e;
        ATTR[c * TE + e] = (ge < E) ? attr[(size_t)ge * 4 + c] : 0.0f;
    }
    for (int i = tid; i < 128 * TE; i += NT) {
        int e = i & 63, c = i >> 6, ge = e0 + e;
        LATSC[c * TE + e] = (ge < E) ? g_lat[(size_t)c * E + ge] : 0.0f;
    }
    for (int i = tid; i < 64 * TE; i += NT) {
        int e = i & 63, c = i >> 6, ge = e0 + e;
        W64S[c * 65 + e] = (ge < E) ? g_w64[(size_t)c * E + ge] : 0.0f;
    }
    __syncthreads();
    for (int i = tid; i < 128 * TE; i += NT) {
        int c = i & 127, e = i >> 7;
        ENVH[c * 65 + e] = g_env0[(size_t)CENT[e] * 128 + c] * 0.25f;
    }
    __syncthreads();

    const float is3 = 0.5773502691896258f;
    for (int i = tid; i < 32 * TE; i += NT) {
        int m = i >> 6, e = i & 63;
        float a0 = ATTR[e], a1 = ATTR[TE + e], a2 = ATTR[2 * TE + e], a3 = ATTR[3 * TE + e];
        float wA = W64S[(2 * m) * 65 + e], wB = W64S[(2 * m + 1) * 65 + e];
        float x0 = wA * a0, x1 = wB * a1, x2 = wB * a2, x3 = wB * a3;
        float y0 = ENVH[(4 * m) * 65 + e],     y1 = ENVH[(4 * m + 1) * 65 + e];
        float y2 = ENVH[(4 * m + 2) * 65 + e], y3 = ENVH[(4 * m + 3) * 65 + e];
        float ss = x0 * y0;
        float vv = (x1 * y1 + x2 * y2 + x3 * y3) * is3;
        LATSC[(128 + 2 * m) * TE + e]     = ss;
        LATSC[(128 + 2 * m + 1) * TE + e] = vv;
        SIN[m * TE + e]        = ss;
        SIN[(32 + m) * TE + e] = vv;
        VIN[(0 * 64 + m) * TE + e]      = x0 * y1 * is3;
        VIN[(1 * 64 + m) * TE + e]      = x0 * y2 * is3;
        VIN[(2 * 64 + m) * TE + e]      = x0 * y3 * is3;
        VIN[(0 * 64 + 32 + m) * TE + e] = x1 * y0 * is3;
        VIN[(1 * 64 + 32 + m) * TE + e] = x2 * y0 * is3;
        VIN[(2 * 64 + 32 + m) * TE + e] = x3 * y0 * is3;
    }

    gemm_tile<64, 32, false>(SIN, Ws0, WBUF, 0.125f, tid,
        [&](int col, int e, float v) { int ge = e0 + e; if (ge < E) g_fn[(size_t)(col * 4) * E + ge] = v; });
    gemm_tile<64, 32, false>(VIN, Wv0, WBUF, 0.125f, tid,
        [&](int col, int e, float v) { int ge = e0 + e; if (ge < E) g_fn[(size_t)(col * 4 + 1) * E + ge] = v; });
    gemm_tile<64, 32, false>(VIN + 64 * TE, Wv0, WBUF, 0.125f, tid,
        [&](int col, int e, float v) { int ge = e0 + e; if (ge < E) g_fn[(size_t)(col * 4 + 2) * E + ge] = v; });
    gemm_tile<64, 32, false>(VIN + 128 * TE, Wv0, WBUF, 0.125f, tid,
        [&](int col, int e, float v) { int ge = e0 + e; if (ge < E) g_fn[(size_t)(col * 4 + 3) * E + ge] = v; });

    gemm_tile<192, 128, true >(LATSC, Wlat10, WBUF, 0.07216878364870323f, tid,
        [&](int col, int e, float v) { ENVH[col * TE + e] = v; });
    gemm_tile<128, 128, false>(ENVH, Wlat11, WBUF, 0.08838834764831845f, tid,
        [&](int col, int e, float v) { VIN[col * TE + e] = v; });

    const float c0 = 0.7071067811865476f;
    for (int i = tid; i < 128 * TE; i += NT) {
        int e = i & 63, c = i >> 6, ge = e0 + e;
        float v = c0 * (LATSC[i] + VIN[i]);
        LATSC[i] = v;
        if (ge < E) g_lat[(size_t)c * E + ge] = v;
    }

    gemm_tile<128, 64, false>(LATSC, Wenv1, WBUF, 0.08838834764831845f, tid,
        [&](int col, int e, float v) { ENVH[col * 65 + e] = v; });

    for (int i = tid; i < 128 * TE; i += NT) {
        int comp = i & 127, e = i >> 7, ge = e0 + e;
        if (ge >= E) continue;
        int m = comp >> 2, cc = comp & 3;
        int row = 2 * m + (cc ? 1 : 0);
        atomicAdd(&g_env1[(size_t)CENT[e] * 128 + comp], ENVH[row * 65 + e] * ATTR[cc * TE + e]);
    }
}

// ============ Kernel D: gather env1, final MLP, output ============
__global__ void __launch_bounds__(NT, 1)
kD(const int* __restrict__ eidx, const float* __restrict__ Wfin0,
   const float* __restrict__ Wfin1, float* __restrict__ out, int E)
{
    extern __shared__ float sm[];
    float* WBUF  = sm;                 // 8320 (weights / transpose s129)
    float* LATSC = sm + 8320;          // 12288
    float* FN    = sm + 20608;         // 8192
    float* ENVH  = sm + 28800;         // 8320
    int*   CENT  = (int*)(sm + 37120); // 64
    const int tid = threadIdx.x, e0 = blockIdx.x * TE;

    for (int i = tid; i < TE; i += NT) { int ge = e0 + i; CENT[i] = (ge < E) ? eidx[ge] : 0; }
    for (int i = tid; i < 128 * TE; i += NT) {
        int e = i & 63, c = i >> 6, ge = e0 + e;
        LATSC[c * TE + e] = (ge < E) ? g_lat[(size_t)c * E + ge] : 0.0f;
        FN[c * TE + e]    = (ge < E) ? g_fn[(size_t)c * E + ge] : 0.0f;
    }
    __syncthreads();
    for (int i = tid; i < 128 * TE; i += NT) {
        int c = i & 127, e = i >> 7;
        ENVH[c * 65 + e] = g_env1[(size_t)CENT[e] * 128 + c] * 0.25f;
    }
    __syncthreads();

    const float is3 = 0.5773502691896258f;
    for (int i = tid; i < 32 * TE; i += NT) {
        int m = i >> 6, e = i & 63;
        float f0 = FN[(4 * m) * TE + e],     f1 = FN[(4 * m + 1) * TE + e];
        float f2 = FN[(4 * m + 2) * TE + e], f3 = FN[(4 * m + 3) * TE + e];
        float y0 = ENVH[(4 * m) * 65 + e],     y1 = ENVH[(4 * m + 1) * 65 + e];
        float y2 = ENVH[(4 * m + 2) * 65 + e], y3 = ENVH[(4 * m + 3) * 65 + e];
        LATSC[(128 + 2 * m) * TE + e]     = f0 * y0;
        LATSC[(128 + 2 * m + 1) * TE + e] = (f1 * y1 + f2 * y2 + f3 * y3) * is3;
    }

    gemm_tile<192, 128, true >(LATSC, Wfin0, WBUF, 0.07216878364870323f, tid,
        [&](int col, int e, float v) { ENVH[col * TE + e] = v; });
    gemm_tile<128, 128, false>(ENVH, Wfin1, WBUF, 0.08838834764831845f, tid,
        [&](int col, int e, float v) { FN[col * TE + e] = v; });

    const float ca = 0.816496580927726f, cb = 0.5773502691896258f;
    for (int i = tid; i < 128 * TE; i += NT) {
        int e = i & 63, c = i >> 6;
        WBUF[e * 129 + c] = ca * LATSC[c * TE + e] + cb * FN[c * TE + e];
    }
    __syncthreads();
    for (int i = tid; i < 128 * TE; i += NT) {
        int c = i & 127, e = i >> 7, ge = e0 + e;
        if (ge < E) out[(size_t)ge * 128 + c] = WBUF[e * 129 + c];
    }
}

extern "C" void kernel_launch(void* const* d_in, const int* in_sizes, int n_in,
                              void* d_out, int out_size)
{
    const int*   eidx   = (const int*)d_in[0];
    const float* attr   = (const float*)d_in[1];
    const float* inv    = (const float*)d_in[2];
    const float* W2b0   = (const float*)d_in[3];
    const float* W2b1   = (const float*)d_in[4];
    const float* Wenv0  = (const float*)d_in[5];
    const float* Wlat10 = (const float*)d_in[6];
    const float* Wlat11 = (const float*)d_in[7];
    const float* Wenv1  = (const float*)d_in[8];
    const float* Ws0    = (const float*)d_in[9];
    const float* Wv0    = (const float*)d_in[10];
    const float* Wfin0  = (const float*)d_in[11];
    const float* Wfin1  = (const float*)d_in[12];

    int E = in_sizes[1] / 4;
    if (E > EMAX) E = EMAX;

    const int smemA = 25408 * (int)sizeof(float);  // 101632 -> 2 CTAs/SM
    const int smemC = 49664 * (int)sizeof(float);
    const int smemD = 37184 * (int)sizeof(float);
    static int attr_done = 0;
    if (!attr_done) {
        cudaFuncSetAttribute(kA, cudaFuncAttributeMaxDynamicSharedMemorySize, smemA);
        cudaFuncSetAttribute(kC, cudaFuncAttributeMaxDynamicSharedMemorySize, smemC);
        cudaFuncSetAttribute(kD, cudaFuncAttributeMaxDynamicSharedMemorySize, smemD);
        attr_done = 1;
    }

    void *p0, *p1;
    cudaGetSymbolAddress(&p0, g_env0);
    cudaGetSymbolAddress(&p1, g_env1);
    cudaMemsetAsync(p0, 0, (size_t)NMAX * 128 * sizeof(float), 0);
    cudaMemsetAsync(p1, 0, (size_t)NMAX * 128 * sizeof(float), 0);

    int nb = (E + TE - 1) / TE;
    kA<<<nb, NT, smemA>>>(eidx, attr, inv, W2b0, W2b1, Wenv0, E);
    kC<<<nb, NT, smemC>>>(eidx, attr, Ws0, Wv0, Wlat10, Wlat11, Wenv1, E);
    kD<<<nb, NT, smemD>>>(eidx, Wfin0, Wfin1, (float*)d_out, E);
}

// round 16
// speedup vs baseline: 1.0097x; 1.0003x over previous
#include <cuda_runtime.h>
#include <math.h>

#define EMAX 200000
#define NMAX 12500
#define TE 64
#define NT 256

__device__ float g_lat[(size_t)128 * EMAX];
__device__ float g_w64[(size_t)64 * EMAX];
__device__ float g_fn [(size_t)128 * EMAX];
__device__ float g_env0[(size_t)NMAX * 128];
__device__ float g_env1[(size_t)NMAX * 128];

__device__ __forceinline__ float silu_f(float v) { return v / (1.0f + __expf(-v)); }

// Tile GEMM v3: warp covers 32 edges x (KOUT/4) cols -> per-warp smem traffic
// hits the crossbar floor (a: 128B contiguous; b: contiguous slab, both
// conflict-free). Thread: 4 edges x CPT cols, packed f32x2 accumulators.
template <int KIN, int KOUT, bool SILU, class Epi>
__device__ __forceinline__ void gemm_tile(const float* __restrict__ Xs,
                                          const float* __restrict__ Wg,
                                          float* __restrict__ Wbuf,
                                          float scale, int tid, Epi epi)
{
    constexpr int CPT = KOUT / 16;   // 8, 4 or 2 cols per thread
    constexpr int NPR = CPT / 2;     // col-pairs per thread
    unsigned long long acc[4][NPR];
#pragma unroll
    for (int i = 0; i < 4; i++)
#pragma unroll
        for (int j = 0; j < NPR; j++) acc[i][j] = 0ull;

    const int lane = tid & 31, wid = tid >> 5;
    const int e_base = (wid & 1) * 32 + (lane & 7) * 4;            // 32-edge half
    const int c_base = (wid >> 1) * (KOUT / 4) + (lane >> 3) * CPT; // 32-col quarter

    for (int kc = 0; kc < KIN; kc += 64) {
        __syncthreads();
        const int rows = (KIN - kc) < 64 ? (KIN - kc) : 64;
        {
            const float4* src = (const float4*)(Wg + (size_t)kc * KOUT);
            float4* dst = (float4*)Wbuf;
            for (int i = tid; i < rows * KOUT / 4; i += NT) dst[i] = src[i];
        }
        __syncthreads();
#pragma unroll 8
        for (int kk = 0; kk < rows; kk++) {
            float4 av = *(const float4*)(Xs + (kc + kk) * TE + e_base);
            unsigned long long a0, a1, a2, a3;
            asm("mov.b64 %0,{%1,%1};" : "=l"(a0) : "f"(av.x));
            asm("mov.b64 %0,{%1,%1};" : "=l"(a1) : "f"(av.y));
            asm("mov.b64 %0,{%1,%1};" : "=l"(a2) : "f"(av.z));
            asm("mov.b64 %0,{%1,%1};" : "=l"(a3) : "f"(av.w));
            const float* wrow = Wbuf + kk * KOUT + c_base;
            unsigned long long b[NPR];
            if (NPR == 1) {
                b[0] = *(const unsigned long long*)wrow;
            } else if (NPR == 2) {
                ulonglong2 bv = *(const ulonglong2*)wrow;
                b[0] = bv.x; b[1] = bv.y;
            } else {
                ulonglong2 bv0 = *(const ulonglong2*)wrow;
                ulonglong2 bv1 = *(const ulonglong2*)(wrow + 4);
                b[0] = bv0.x; b[1] = bv0.y; b[2] = bv1.x; b[3] = bv1.y;
            }
#pragma unroll
            for (int j = 0; j < NPR; j++) {
                asm("fma.rn.f32x2 %0,%1,%2,%0;" : "+l"(acc[0][j]) : "l"(a0), "l"(b[j]));
                asm("fma.rn.f32x2 %0,%1,%2,%0;" : "+l"(acc[1][j]) : "l"(a1), "l"(b[j]));
                asm("fma.rn.f32x2 %0,%1,%2,%0;" : "+l"(acc[2][j]) : "l"(a2), "l"(b[j]));
                asm("fma.rn.f32x2 %0,%1,%2,%0;" : "+l"(acc[3][j]) : "l"(a3), "l"(b[j]));
            }
        }
    }
#pragma unroll
    for (int j = 0; j < NPR; j++) {
        int col = c_base + 2 * j;
#pragma unroll
        for (int i = 0; i < 4; i++) {
            float lo, hi;
            asm("mov.b64 {%0,%1},%2;" : "=f"(lo), "=f"(hi) : "l"(acc[i][j]));
            lo *= scale; hi *= scale;
            if (SILU) { lo = silu_f(lo); hi = silu_f(hi); }
            epi(col, e_base + i, lo);
            epi(col + 1, e_base + i, hi);
        }
    }
    __syncthreads();
}

// ============ Kernel A: lat = mlp2(inv); w = lat@Wenv0; scatter env0 ============
// smem 101.6KB (WT aliases dead XS+H) -> 2 CTAs/SM.
__global__ void __launch_bounds__(NT, 2)
kA(const int* __restrict__ eidx, const float* __restrict__ attr,
   const float* __restrict__ inv, const float* __restrict__ W2b0,
   const float* __restrict__ W2b1, const float* __restrict__ Wenv0, int E)
{
    extern __shared__ float sm[];
    float* WBUF = sm;                 // 8192
    float* XS   = sm + 8192;          // 512
    float* H    = sm + 8704;          // 8192
    float* LAT  = sm + 16896;         // 8192
    float* ATTR = sm + 25088;         // 256
    int*   CENT = (int*)(sm + 25344); // 64
    float* WT   = sm + 8192;          // 8320 alias over XS+H (dead by gemm3)
    const int tid = threadIdx.x, e0 = blockIdx.x * TE;

    for (int i = tid; i < TE; i += NT) { int ge = e0 + i; CENT[i] = (ge < E) ? eidx[ge] : 0; }
    for (int i = tid; i < 4 * TE; i += NT) {
        int e = i >> 2, c = i & 3, ge = e0 + e;
        ATTR[c * TE + e] = (ge < E) ? attr[(size_t)ge * 4 + c] : 0.0f;
    }
    for (int i = tid; i < 8 * TE; i += NT) {
        int e = i >> 3, c = i & 7, ge = e0 + e;
        XS[c * TE + e] = (ge < E) ? inv[(size_t)ge * 8 + c] : 0.0f;
    }

    gemm_tile<8, 128, true >(XS, W2b0, WBUF, 0.35355339059327373f, tid,
        [&](int col, int e, float v) { H[col * TE + e] = v; });
    gemm_tile<128, 128, false>(H, W2b1, WBUF, 0.08838834764831845f, tid,
        [&](int col, int e, float v) { LAT[col * TE + e] = v; });

    for (int i = tid; i < 128 * TE; i += NT) {
        int e = i & 63, c = i >> 6, ge = e0 + e;
        if (ge < E) g_lat[(size_t)c * E + ge] = LAT[c * TE + e];
    }

    gemm_tile<128, 128, false>(LAT, Wenv0, WBUF, 0.08838834764831845f, tid,
        [&](int col, int e, float v) { WT[col * 65 + e] = v; });

    for (int i = tid; i < 64 * TE; i += NT) {
        int e = i & 63, c = i >> 6, ge = e0 + e;
        if (ge < E) g_w64[(size_t)c * E + ge] = WT[c * 65 + e];
    }
    for (int i = tid; i < 128 * TE; i += NT) {
        int comp = i & 127, e = i >> 7, ge = e0 + e;
        if (ge >= E) continue;
        int m = comp >> 2, cc = comp & 3;
        int row = 64 + 2 * m + (cc ? 1 : 0);
        atomicAdd(&g_env0[(size_t)CENT[e] * 128 + comp], WT[row * 65 + e] * ATTR[cc * TE + e]);
    }
}

// ============ Kernel C: tensor products, Ws0/Wv0, lat update, scatter env1 ============
__global__ void __launch_bounds__(NT, 1)
kC(const int* __restrict__ eidx, const float* __restrict__ attr,
   const float* __restrict__ Ws0, const float* __restrict__ Wv0,
   const float* __restrict__ Wlat10, const float* __restrict__ Wlat11,
   const float* __restrict__ Wenv1, int E)
{
    extern __shared__ float sm[];
    float* WBUF  = sm;                 // 8192
    float* LATSC = sm + 8192;          // 12288
    float* ENVH  = sm + 20480;         // 8320 (env0 s65 -> H s64 -> w1 s65)
    float* W64S  = sm + 28800;         // 4160 (stride 65)
    float* SIN   = sm + 32960;         // 4096
    float* VIN   = sm + 37056;         // 12288 (v_in -> new_lat)
    float* ATTR  = sm + 49344;         // 256
    int*   CENT  = (int*)(sm + 49600); // 64
    const int tid = threadIdx.x, e0 = blockIdx.x * TE;

    for (int i = tid; i < TE; i += NT) { int ge = e0 + i; CENT[i] = (ge < E) ? eidx[ge] : 0; }
    for (int i = tid; i < 4 * TE; i += NT) {
        int e = i >> 2, c = i & 3, ge = e0 + e;
        ATTR[c * TE + e] = (ge < E) ? attr[(size_t)ge * 4 + c] : 0.0f;
    }
    for (int i = tid; i < 128 * TE; i += NT) {
        int e = i & 63, c = i >> 6, ge = e0 + e;
        LATSC[c * TE + e] = (ge < E) ? g_lat[(size_t)c * E + ge] : 0.0f;
    }
    for (int i = tid; i < 64 * TE; i += NT) {
        int e = i & 63, c = i >> 6, ge = e0 + e;
        W64S[c * 65 + e] = (ge < E) ? g_w64[(size_t)c * E + ge] : 0.0f;
    }
    __syncthreads();
    for (int i = tid; i < 128 * TE; i += NT) {
        int c = i & 127, e = i >> 7;
        ENVH[c * 65 + e] = g_env0[(size_t)CENT[e] * 128 + c] * 0.25f;
    }
    __syncthreads();

    const float is3 = 0.5773502691896258f;
    for (int i = tid; i < 32 * TE; i += NT) {
        int m = i >> 6, e = i & 63;
        float a0 = ATTR[e], a1 = ATTR[TE + e], a2 = ATTR[2 * TE + e], a3 = ATTR[3 * TE + e];
        float wA = W64S[(2 * m) * 65 + e], wB = W64S[(2 * m + 1) * 65 + e];
        float x0 = wA * a0, x1 = wB * a1, x2 = wB * a2, x3 = wB * a3;
        float y0 = ENVH[(4 * m) * 65 + e],     y1 = ENVH[(4 * m + 1) * 65 + e];
        float y2 = ENVH[(4 * m + 2) * 65 + e], y3 = ENVH[(4 * m + 3) * 65 + e];
        float ss = x0 * y0;
        float vv = (x1 * y1 + x2 * y2 + x3 * y3) * is3;
        LATSC[(128 + 2 * m) * TE + e]     = ss;
        LATSC[(128 + 2 * m + 1) * TE + e] = vv;
        SIN[m * TE + e]        = ss;
        SIN[(32 + m) * TE + e] = vv;
        VIN[(0 * 64 + m) * TE + e]      = x0 * y1 * is3;
        VIN[(1 * 64 + m) * TE + e]      = x0 * y2 * is3;
        VIN[(2 * 64 + m) * TE + e]      = x0 * y3 * is3;
        VIN[(0 * 64 + 32 + m) * TE + e] = x1 * y0 * is3;
        VIN[(1 * 64 + 32 + m) * TE + e] = x2 * y0 * is3;
        VIN[(2 * 64 + 32 + m) * TE + e] = x3 * y0 * is3;
    }

    gemm_tile<64, 32, false>(SIN, Ws0, WBUF, 0.125f, tid,
        [&](int col, int e, float v) { int ge = e0 + e; if (ge < E) g_fn[(size_t)(col * 4) * E + ge] = v; });
    gemm_tile<64, 32, false>(VIN, Wv0, WBUF, 0.125f, tid,
        [&](int col, int e, float v) { int ge = e0 + e; if (ge < E) g_fn[(size_t)(col * 4 + 1) * E + ge] = v; });
    gemm_tile<64, 32, false>(VIN + 64 * TE, Wv0, WBUF, 0.125f, tid,
        [&](int col, int e, float v) { int ge = e0 + e; if (ge < E) g_fn[(size_t)(col * 4 + 2) * E + ge] = v; });
    gemm_tile<64, 32, false>(VIN + 128 * TE, Wv0, WBUF, 0.125f, tid,
        [&](int col, int e, float v) { int ge = e0 + e; if (ge < E) g_fn[(size_t)(col * 4 + 3) * E + ge] = v; });

    gemm_tile<192, 128, true >(LATSC, Wlat10, WBUF, 0.07216878364870323f, tid,
        [&](int col, int e, float v) { ENVH[col * TE + e] = v; });
    gemm_tile<128, 128, false>(ENVH, Wlat11, WBUF, 0.08838834764831845f, tid,
        [&](int col, int e, float v) { VIN[col * TE + e] = v; });

    const float c0 = 0.7071067811865476f;
    for (int i = tid; i < 128 * TE; i += NT) {
        int e = i & 63, c = i >> 6, ge = e0 + e;
        float v = c0 * (LATSC[i] + VIN[i]);
        LATSC[i] = v;
        if (ge < E) g_lat[(size_t)c * E + ge] = v;
    }

    gemm_tile<128, 64, false>(LATSC, Wenv1, WBUF, 0.08838834764831845f, tid,
        [&](int col, int e, float v) { ENVH[col * 65 + e] = v; });

    for (int i = tid; i < 128 * TE; i += NT) {
        int comp = i & 127, e = i >> 7, ge = e0 + e;
        if (ge >= E) continue;
        int m = comp >> 2, cc = comp & 3;
        int row = 2 * m + (cc ? 1 : 0);
        atomicAdd(&g_env1[(size_t)CENT[e] * 128 + comp], ENVH[row * 65 + e] * ATTR[cc * TE + e]);
    }
}

// ============ Kernel D: gather env1, final MLP, output ============
__global__ void __launch_bounds__(NT, 1)
kD(const int* __restrict__ eidx, const float* __restrict__ Wfin0,
   const float* __restrict__ Wfin1, float* __restrict__ out, int E)
{
    extern __shared__ float sm[];
    float* WBUF  = sm;                 // 8320 (weights / transpose s129)
    float* LATSC = sm + 8320;          // 12288
    float* FN    = sm + 20608;         // 8192
    float* ENVH  = sm + 28800;         // 8320
    int*   CENT  = (int*)(sm + 37120); // 64
    const int tid = threadIdx.x, e0 = blockIdx.x * TE;

    for (int i = tid; i < TE; i += NT) { int ge = e0 + i; CENT[i] = (ge < E) ? eidx[ge] : 0; }
    for (int i = tid; i < 128 * TE; i += NT) {
        int e = i & 63, c = i >> 6, ge = e0 + e;
        LATSC[c * TE + e] = (ge < E) ? g_lat[(size_t)c * E + ge] : 0.0f;
        FN[c * TE + e]    = (ge < E) ? g_fn[(size_t)c * E + ge] : 0.0f;
    }
    __syncthreads();
    for (int i = tid; i < 128 * TE; i += NT) {
        int c = i & 127, e = i >> 7;
        ENVH[c * 65 + e] = g_env1[(size_t)CENT[e] * 128 + c] * 0.25f;
    }
    __syncthreads();

    const float is3 = 0.5773502691896258f;
    for (int i = tid; i < 32 * TE; i += NT) {
        int m = i >> 6, e = i & 63;
        float f0 = FN[(4 * m) * TE + e],     f1 = FN[(4 * m + 1) * TE + e];
        float f2 = FN[(4 * m + 2) * TE + e], f3 = FN[(4 * m + 3) * TE + e];
        float y0 = ENVH[(4 * m) * 65 + e],     y1 = ENVH[(4 * m + 1) * 65 + e];
        float y2 = ENVH[(4 * m + 2) * 65 + e], y3 = ENVH[(4 * m + 3) * 65 + e];
        LATSC[(128 + 2 * m) * TE + e]     = f0 * y0;
        LATSC[(128 + 2 * m + 1) * TE + e] = (f1 * y1 + f2 * y2 + f3 * y3) * is3;
    }

    gemm_tile<192, 128, true >(LATSC, Wfin0, WBUF, 0.07216878364870323f, tid,
        [&](int col, int e, float v) { ENVH[col * TE + e] = v; });
    gemm_tile<128, 128, false>(ENVH, Wfin1, WBUF, 0.08838834764831845f, tid,
        [&](int col, int e, float v) { FN[col * TE + e] = v; });

    const float ca = 0.816496580927726f, cb = 0.5773502691896258f;
    for (int i = tid; i < 128 * TE; i += NT) {
        int e = i & 63, c = i >> 6;
        WBUF[e * 129 + c] = ca * LATSC[c * TE + e] + cb * FN[c * TE + e];
    }
    __syncthreads();
    for (int i = tid; i < 128 * TE; i += NT) {
        int c = i & 127, e = i >> 7, ge = e0 + e;
        if (ge < E) out[(size_t)ge * 128 + c] = WBUF[e * 129 + c];
    }
}

extern "C" void kernel_launch(void* const* d_in, const int* in_sizes, int n_in,
                              void* d_out, int out_size)
{
    const int*   eidx   = (const int*)d_in[0];
    const float* attr   = (const float*)d_in[1];
    const float* inv    = (const float*)d_in[2];
    const float* W2b0   = (const float*)d_in[3];
    const float* W2b1   = (const float*)d_in[4];
    const float* Wenv0  = (const float*)d_in[5];
    const float* Wlat10 = (const float*)d_in[6];
    const float* Wlat11 = (const float*)d_in[7];
    const float* Wenv1  = (const float*)d_in[8];
    const float* Ws0    = (const float*)d_in[9];
    const float* Wv0    = (const float*)d_in[10];
    const float* Wfin0  = (const float*)d_in[11];
    const float* Wfin1  = (const float*)d_in[12];

    int E = in_sizes[1] / 4;
    if (E > EMAX) E = EMAX;

    const int smemA = 25408 * (int)sizeof(float);  // 101632 -> 2 CTAs/SM
    const int smemC = 49664 * (int)sizeof(float);
    const int smemD = 37184 * (int)sizeof(float);
    static int attr_done = 0;
    if (!attr_done) {
        cudaFuncSetAttribute(kA, cudaFuncAttributeMaxDynamicSharedMemorySize, smemA);
        cudaFuncSetAttribute(kC, cudaFuncAttributeMaxDynamicSharedMemorySize, smemC);
        cudaFuncSetAttribute(kD, cudaFuncAttributeMaxDynamicSharedMemorySize, smemD);
        attr_done = 1;
    }

    void *p0, *p1;
    cudaGetSymbolAddress(&p0, g_env0);
    cudaGetSymbolAddress(&p1, g_env1);
    cudaMemsetAsync(p0, 0, (size_t)NMAX * 128 * sizeof(float), 0);
    cudaMemsetAsync(p1, 0, (size_t)NMAX * 128 * sizeof(float), 0);

    int nb = (E + TE - 1) / TE;
    kA<<<nb, NT, smemA>>>(eidx, attr, inv, W2b0, W2b1, Wenv0, E);
    kC<<<nb, NT, smemC>>>(eidx, attr, Ws0, Wv0, Wlat10, Wlat11, Wenv1, E);
    kD<<<nb, NT, smemD>>>(eidx, Wfin0, Wfin1, (float*)d_out, E);
}